// round 5
// baseline (speedup 1.0000x reference)
#include <cuda_runtime.h>
#include <cuda_bf16.h>
#include <math.h>
#include <stdint.h>

#define B_ 32
#define T_ 2048
#define D_ 512
#define U_ 512

// ---------------------------------------------------------------------------
// score tiling: CTA = 64 rows x full U. 8 warps 2(M) x 4(N), warp tile 32x16.
// N-tile 64 u, k chunks of 128 (4 ksteps of k32), B double buffered, int8 limbs.
// ---------------------------------------------------------------------------
#define MT 64
#define A_STR 528            // bytes per A row (512 + 16; 528%128==16 -> conflict-free)
#define B_STR 144            // bytes per B row (128 + 16)

// smem byte offsets
#define SM_A1   0            // 64*528 = 33792
#define SM_A2   33792        // -> 67584
#define SM_SA   67584        // 64 f32 row scales
#define SM_QS   67840        // 64 f32 row quant scales (127/sa)
#define SM_PQ   68096        // 512 f32
#define SM_V    70144        // 512 f32
#define SM_SB   72192        // 512 f32 col scales
#define SM_RED  74240        // 64*4 f32
#define SM_B    75264        // 2 bufs x (limb1 9216 + limb2 9216) = 36864
#define SM_B_BUF 18432
#define SM_B_L2  9216
#define SMEM_TOTAL 112128

#define INV254   (1.0f / 254.0f)
#define INV127SQ (1.0f / 16129.0f)

// ---------------------------------------------------------------------------
// scratch globals
// ---------------------------------------------------------------------------
__device__ float g_projq[B_ * U_];
__device__ float g_score[B_ * T_];
__device__ float g_sb[U_];
__device__ __align__(16) signed char g_W1q1[U_ * D_];  // [n][k]
__device__ __align__(16) signed char g_W1q2[U_ * D_];

// ---------------------------------------------------------------------------
// PTX helpers (sm_80+ only; harness targets compute_103 => no 'a' features)
// ---------------------------------------------------------------------------
__device__ __forceinline__ uint32_t smem_u32(const void* p) {
    uint32_t a;
    asm("{ .reg .u64 t; cvta.to.shared.u64 t, %1; cvt.u32.u64 %0, t; }"
        : "=r"(a) : "l"(p));
    return a;
}
__device__ __forceinline__ void cp_async16(uint32_t dst, const void* src) {
    asm volatile("cp.async.cg.shared.global [%0], [%1], 16;"
                 :: "r"(dst), "l"(src) : "memory");
}
#define CP_COMMIT() asm volatile("cp.async.commit_group;" ::: "memory")
#define CP_WAIT(n)  asm volatile("cp.async.wait_group %0;" :: "n"(n) : "memory")

__device__ __forceinline__ void ldsm4(uint32_t* r, uint32_t addr) {
    asm volatile("ldmatrix.sync.aligned.m8n8.x4.shared.b16 {%0,%1,%2,%3}, [%4];"
                 : "=r"(r[0]), "=r"(r[1]), "=r"(r[2]), "=r"(r[3]) : "r"(addr));
}
__device__ __forceinline__ void mma_s8(int* d, const uint32_t* a,
                                       uint32_t b0, uint32_t b1) {
    asm volatile(
        "mma.sync.aligned.m16n8k32.row.col.s32.s8.s8.s32 "
        "{%0,%1,%2,%3}, {%4,%5,%6,%7}, {%8,%9}, {%0,%1,%2,%3};"
        : "+r"(d[0]), "+r"(d[1]), "+r"(d[2]), "+r"(d[3])
        : "r"(a[0]), "r"(a[1]), "r"(a[2]), "r"(a[3]), "r"(b0), "r"(b1));
}

__device__ __forceinline__ float tanh_fast(float x) {
    float xc = fminf(fmaxf(x, -9.0f), 9.0f);
    float e = __expf(2.0f * xc);
    return (e - 1.0f) / (e + 1.0f);
}

// ---------------------------------------------------------------------------
// W1 transpose + 2-limb int8 quantization (per-column scale)
// block = u column; 512 threads over k
// ---------------------------------------------------------------------------
__global__ void w1quant_kernel(const float* __restrict__ W1) {
    __shared__ float red[512];
    int u = blockIdx.x;
    int k = threadIdx.x;
    float x = W1[k * U_ + u];
    red[k] = fabsf(x);
    __syncthreads();
    for (int off = 256; off > 0; off >>= 1) {
        if (k < off) red[k] = fmaxf(red[k], red[k + off]);
        __syncthreads();
    }
    float s = fmaxf(red[0], 1e-20f);
    float qs = 127.0f / s;
    int a1 = __float2int_rn(x * qs);
    float r = x * qs - (float)a1;
    int a2 = __float2int_rn(r * 254.0f);
    g_W1q1[u * D_ + k] = (signed char)a1;
    g_W1q2[u * D_ + k] = (signed char)a2;
    if (k == 0) g_sb[u] = s;
}

// ---------------------------------------------------------------------------
// proj_q[b,u] = query[b,:] @ W2[:,u] + b2[u] + b1[u]
// ---------------------------------------------------------------------------
__global__ void projq_kernel(const float* __restrict__ query,
                             const float* __restrict__ W2,
                             const float* __restrict__ b1,
                             const float* __restrict__ b2) {
    __shared__ float q[D_];
    int b = blockIdx.x;
    for (int i = threadIdx.x; i < D_; i += blockDim.x) q[i] = query[b * D_ + i];
    __syncthreads();
    int u = threadIdx.x;
    float acc = b1[u] + b2[u];
#pragma unroll 8
    for (int d = 0; d < D_; d++) acc += q[d] * W2[d * U_ + u];
    g_projq[b * U_ + u] = acc;
}

// ---------------------------------------------------------------------------
// score kernel: int8 2-limb mma.sync GEMM + fused tanh/V epilogue
// ---------------------------------------------------------------------------
__global__ void __launch_bounds__(256, 2)
score_kernel(const float* __restrict__ values, const float* __restrict__ V) {
    extern __shared__ char smem[];
    const uint32_t sb = smem_u32(smem);
    const int tid = threadIdx.x;
    const int wid = tid >> 5;
    const int lane = tid & 31;
    const int wm = wid & 1;          // 32-row group
    const int wn = wid >> 1;         // 16-u group within 64-u N-tile
    const int row0 = blockIdx.x * MT;
    const int b = row0 / T_;

    // ---- preload B chunk 0 (nt=0,kc=0) ----
    {
#pragma unroll
        for (int it = 0; it < 4; it++) {
            int idx = tid + it * 256;          // 1024: [limb(1)|n(6)|c(3)]
            int limb = idx >> 9, rem = idx & 511;
            int n = rem >> 3, c = rem & 7;
            uint32_t dst = sb + SM_B + limb * SM_B_L2 + n * B_STR + c * 16;
            const signed char* src = (limb ? g_W1q2 : g_W1q1) + (size_t)n * D_ + c * 16;
            cp_async16(dst, src);
        }
        CP_COMMIT();
    }

    // ---- stage pq, V, sb ----
    {
        float* pqs = (float*)(smem + SM_PQ);
        float* Vs = (float*)(smem + SM_V);
        float* sbs = (float*)(smem + SM_SB);
        for (int i = tid; i < U_; i += 256) {
            pqs[i] = g_projq[b * U_ + i];
            Vs[i] = V[i];
            sbs[i] = g_sb[i];
        }
    }

    // ---- pass 1: per-row max of |values| (each warp: 8 rows) ----
    {
        float* sas = (float*)(smem + SM_SA);
        float* qss = (float*)(smem + SM_QS);
#pragma unroll
        for (int rr = 0; rr < 8; rr++) {
            int r = wid * 8 + rr;
            const float* vr = values + (size_t)(row0 + r) * D_;
            float m = 0.0f;
#pragma unroll
            for (int c = 0; c < 16; c++) m = fmaxf(m, fabsf(vr[lane + c * 32]));
#pragma unroll
            for (int o = 16; o > 0; o >>= 1)
                m = fmaxf(m, __shfl_xor_sync(0xffffffffu, m, o));
            if (lane == 0) {
                float s = fmaxf(m, 1e-20f);
                sas[r] = s;
                qss[r] = 127.0f / s;
            }
        }
    }
    __syncthreads();

    // ---- pass 2: quantize A rows to 2 int8 limbs in smem ----
    {
        const float4* src = (const float4*)(values + (size_t)row0 * D_);
        const float* qss = (const float*)(smem + SM_QS);
#pragma unroll
        for (int it = 0; it < 32; it++) {
            int idx = tid + it * 256;          // 8192 float4
            int r = idx >> 7, c = idx & 127;
            float4 v = src[idx];
            float qs = qss[r];
            int i0 = __float2int_rn(v.x * qs);
            int i1 = __float2int_rn(v.y * qs);
            int i2 = __float2int_rn(v.z * qs);
            int i3 = __float2int_rn(v.w * qs);
            int j0 = __float2int_rn((v.x * qs - (float)i0) * 254.0f);
            int j1 = __float2int_rn((v.y * qs - (float)i1) * 254.0f);
            int j2 = __float2int_rn((v.z * qs - (float)i2) * 254.0f);
            int j3 = __float2int_rn((v.w * qs - (float)i3) * 254.0f);
            uint32_t w1 = (i0 & 0xFF) | ((i1 & 0xFF) << 8) | ((i2 & 0xFF) << 16) | ((uint32_t)(i3 & 0xFF) << 24);
            uint32_t w2 = (j0 & 0xFF) | ((j1 & 0xFF) << 8) | ((j2 & 0xFF) << 16) | ((uint32_t)(j3 & 0xFF) << 24);
            uint32_t off = r * A_STR + c * 4;
            *(uint32_t*)(smem + SM_A1 + off) = w1;
            *(uint32_t*)(smem + SM_A2 + off) = w2;
        }
    }

    // ---- ldmatrix lane bases ----
    const uint32_t a_lane = (uint32_t)(((lane & 7) + ((lane >> 3) & 1) * 8) * A_STR
                                       + (lane >> 4) * 16);
    const uint32_t a_base = sb + SM_A1 + (uint32_t)(wm * 32) * A_STR + a_lane;
    const uint32_t b_lane = (uint32_t)((lane & 15) * B_STR + (lane >> 4) * 16);
    const uint32_t b_base = sb + SM_B + (uint32_t)(wn * 16) * B_STR + b_lane;

    int hi[2][2][4], mid[2][2][4];
#pragma unroll
    for (int mf = 0; mf < 2; mf++)
#pragma unroll
        for (int nf = 0; nf < 2; nf++)
#pragma unroll
            for (int j = 0; j < 4; j++) { hi[mf][nf][j] = 0; mid[mf][nf][j] = 0; }
    float sp[4] = {0.f, 0.f, 0.f, 0.f};

    const float* pqs = (const float*)(smem + SM_PQ);
    const float* Vs = (const float*)(smem + SM_V);
    const float* sbs = (const float*)(smem + SM_SB);
    const float* sas = (const float*)(smem + SM_SA);

    for (int i = 0; i < 32; i++) {             // nt = i>>2, kc = i&3
        const int nt = i >> 2;
        const int kc = i & 3;
        const int buf = i & 1;

        if (i + 1 < 32) {                      // prefetch next B chunk
            const int nn = (i + 1) >> 2, nk = (i + 1) & 3, nb = (i + 1) & 1;
#pragma unroll
            for (int it = 0; it < 4; it++) {
                int idx = tid + it * 256;
                int limb = idx >> 9, rem = idx & 511;
                int n = rem >> 3, c = rem & 7;
                uint32_t dst = sb + SM_B + nb * SM_B_BUF + limb * SM_B_L2 + n * B_STR + c * 16;
                const signed char* src = (limb ? g_W1q2 : g_W1q1)
                                         + (size_t)(nn * 64 + n) * D_ + nk * 128 + c * 16;
                cp_async16(dst, src);
            }
            CP_COMMIT();
            CP_WAIT(1);
        } else {
            CP_WAIT(0);
        }
        __syncthreads();

        // ---- compute chunk: 4 ksteps of k32 ----
        const uint32_t ab = a_base + (uint32_t)kc * 128;
        const uint32_t bb = b_base + (uint32_t)buf * SM_B_BUF;
#pragma unroll
        for (int ks = 0; ks < 4; ks++) {
            uint32_t a1[2][4], a2[2][4], b1[4], b2[4];
            ldsm4(a1[0], ab + ks * 32);
            ldsm4(a1[1], ab + 16 * A_STR + ks * 32);
            ldsm4(a2[0], ab + SM_A2 + ks * 32);
            ldsm4(a2[1], ab + SM_A2 + 16 * A_STR + ks * 32);
            ldsm4(b1, bb + ks * 32);
            ldsm4(b2, bb + SM_B_L2 + ks * 32);
#pragma unroll
            for (int mf = 0; mf < 2; mf++) {
                mma_s8(hi[mf][0], a1[mf], b1[0], b1[2]);
                mma_s8(mid[mf][0], a1[mf], b2[0], b2[2]);
                mma_s8(mid[mf][0], a2[mf], b1[0], b1[2]);
                mma_s8(hi[mf][1], a1[mf], b1[1], b1[3]);
                mma_s8(mid[mf][1], a1[mf], b2[1], b2[3]);
                mma_s8(mid[mf][1], a2[mf], b1[1], b1[3]);
            }
        }

        if (kc == 3) {
            // ---- epilogue for N-tile nt ----
#pragma unroll
            for (int mf = 0; mf < 2; mf++) {
                int r_lo = wm * 32 + mf * 16 + (lane >> 2);
                float fa_lo = sas[r_lo] * INV127SQ;
                float fa_hi = sas[r_lo + 8] * INV127SQ;
#pragma unroll
                for (int nf = 0; nf < 2; nf++) {
                    int u0 = nt * 64 + wn * 16 + nf * 8 + (lane & 3) * 2;
                    int u1 = u0 + 1;
                    float sb0 = sbs[u0], sb1 = sbs[u1];
                    float pq0 = pqs[u0], pq1 = pqs[u1];
                    float v0 = Vs[u0], v1 = Vs[u1];
                    float p00 = fmaf((float)mid[mf][nf][0], INV254, (float)hi[mf][nf][0]) * (fa_lo * sb0) + pq0;
                    float p01 = fmaf((float)mid[mf][nf][1], INV254, (float)hi[mf][nf][1]) * (fa_lo * sb1) + pq1;
                    float p10 = fmaf((float)mid[mf][nf][2], INV254, (float)hi[mf][nf][2]) * (fa_hi * sb0) + pq0;
                    float p11 = fmaf((float)mid[mf][nf][3], INV254, (float)hi[mf][nf][3]) * (fa_hi * sb1) + pq1;
                    sp[mf * 2 + 0] += tanh_fast(p00) * v0 + tanh_fast(p01) * v1;
                    sp[mf * 2 + 1] += tanh_fast(p10) * v0 + tanh_fast(p11) * v1;
#pragma unroll
                    for (int j = 0; j < 4; j++) { hi[mf][nf][j] = 0; mid[mf][nf][j] = 0; }
                }
            }
        }
        __syncthreads();
    }

    // ---- reduce score partials ----
#pragma unroll
    for (int j = 0; j < 4; j++) {
        sp[j] += __shfl_xor_sync(0xffffffffu, sp[j], 1);
        sp[j] += __shfl_xor_sync(0xffffffffu, sp[j], 2);
    }
    float* red = (float*)(smem + SM_RED);
    if ((lane & 3) == 0) {
        int g = lane >> 2;
#pragma unroll
        for (int mf = 0; mf < 2; mf++) {
            int r0 = wm * 32 + mf * 16 + g;
            red[r0 * 4 + wn] = sp[mf * 2 + 0];
            red[(r0 + 8) * 4 + wn] = sp[mf * 2 + 1];
        }
    }
    __syncthreads();
    if (tid < MT) {
        g_score[row0 + tid] = red[tid * 4] + red[tid * 4 + 1]
                            + red[tid * 4 + 2] + red[tid * 4 + 3];
    }
}

// ---------------------------------------------------------------------------
// softmax over T per batch -> weights; zero context region
// ---------------------------------------------------------------------------
__global__ void softmax_kernel(float* __restrict__ out) {
    __shared__ float sdata[256];
    const int b = blockIdx.x, tid = threadIdx.x;
    float s[8];
    float mx = -1e30f;
#pragma unroll
    for (int i = 0; i < 8; i++) {
        s[i] = g_score[b * T_ + tid + i * 256];
        mx = fmaxf(mx, s[i]);
    }
    sdata[tid] = mx;
    __syncthreads();
    for (int off = 128; off > 0; off >>= 1) {
        if (tid < off) sdata[tid] = fmaxf(sdata[tid], sdata[tid + off]);
        __syncthreads();
    }
    mx = sdata[0];
    __syncthreads();
    float sum = 0.f;
#pragma unroll
    for (int i = 0; i < 8; i++) {
        s[i] = __expf(s[i] - mx);
        sum += s[i];
    }
    sdata[tid] = sum;
    __syncthreads();
    for (int off = 128; off > 0; off >>= 1) {
        if (tid < off) sdata[tid] += sdata[tid + off];
        __syncthreads();
    }
    float inv = 1.0f / sdata[0];
    float* w = out + B_ * D_;
#pragma unroll
    for (int i = 0; i < 8; i++) w[b * T_ + tid + i * 256] = s[i] * inv;

    out[b * D_ + tid] = 0.f;
    out[b * D_ + 256 + tid] = 0.f;
}

// ---------------------------------------------------------------------------
// context[b,d] = sum_t w[b,t] * values[b,t,d]
// ---------------------------------------------------------------------------
__global__ void __launch_bounds__(128)
context_kernel(const float* __restrict__ values, float* __restrict__ out) {
    const int b = blockIdx.x;
    const int t0 = blockIdx.y * 128;
    const int tid = threadIdx.x;
    __shared__ float ws[128];
    ws[tid] = out[B_ * D_ + b * T_ + t0 + tid];
    __syncthreads();
    const float4* vp = (const float4*)(values + ((size_t)b * T_ + t0) * D_) + tid;
    float ax = 0.f, ay = 0.f, az = 0.f, aw = 0.f;
#pragma unroll 4
    for (int tt = 0; tt < 128; tt++) {
        float w = ws[tt];
        float4 v = vp[tt * 128];
        ax += w * v.x; ay += w * v.y; az += w * v.z; aw += w * v.w;
    }
    float* o = out + b * D_ + tid * 4;
    atomicAdd(o + 0, ax);
    atomicAdd(o + 1, ay);
    atomicAdd(o + 2, az);
    atomicAdd(o + 3, aw);
}

// ---------------------------------------------------------------------------
extern "C" void kernel_launch(void* const* d_in, const int* in_sizes, int n_in,
                              void* d_out, int out_size) {
    const float* values = (const float*)d_in[0];  // [B,T,D]
    const float* query  = (const float*)d_in[1];  // [B,D]
    const float* W1     = (const float*)d_in[2];  // [D,U]
    const float* b1     = (const float*)d_in[3];  // [U]
    const float* W2     = (const float*)d_in[4];  // [D,U]
    const float* b2     = (const float*)d_in[5];  // [U]
    const float* V      = (const float*)d_in[6];  // [U,1]
    // d_in[7] = bV: softmax shift-invariant -> unused
    float* out = (float*)d_out;                   // [B*D context | B*T weights]

    cudaFuncSetAttribute(score_kernel,
                         cudaFuncAttributeMaxDynamicSharedMemorySize, SMEM_TOTAL);

    w1quant_kernel<<<U_, D_>>>(W1);
    projq_kernel<<<B_, U_>>>(query, W2, b1, b2);
    score_kernel<<<(B_ * T_) / MT, 256, SMEM_TOTAL>>>(values, V);
    softmax_kernel<<<B_, 256>>>(out);
    context_kernel<<<dim3(B_, 16), 128>>>(values, out);
}

// round 6
// speedup vs baseline: 1.7011x; 1.7011x over previous
#include <cuda_runtime.h>
#include <cuda_bf16.h>
#include <math.h>
#include <stdint.h>

#define B_ 32
#define T_ 2048
#define D_ 512
#define U_ 512

// ---------------------------------------------------------------------------
// score-kernel tiling (R3 shape): CTA = 64 rows x full U, 8 warps 2(M) x 4(N),
// warp tile 32x16, N-tiles of 64 u, B chunks k=128 double-buffered.
// ---------------------------------------------------------------------------
#define MT 64
#define NTILE 64
#define KCH 128
#define A_STRIDE_B 1040       // 520 bf16 per row; %128==16 -> conflict-free ldsm
#define B_STRIDE_B 272        // 136 bf16 per row

// smem byte offsets
#define SM_A_HI   0
#define SM_A_LO   66560                   // 64*1040
#define SM_B      133120                  // 2 bufs x (hi 17408 + lo 17408)
#define SM_B_BUF  34816
#define SM_B_LO   17408
#define SM_PQ     202752
#define SM_V      204800
#define SM_RED    206848
#define SMEM_TOTAL 207872

// ---------------------------------------------------------------------------
// scratch globals
// ---------------------------------------------------------------------------
__device__ float g_projq[B_ * U_];
__device__ float g_score[B_ * T_];
__device__ __align__(16) __nv_bfloat16 g_W1t_hi[U_ * D_];  // [n][k]
__device__ __align__(16) __nv_bfloat16 g_W1t_lo[U_ * D_];

// ---------------------------------------------------------------------------
// PTX helpers (sm_80+ only)
// ---------------------------------------------------------------------------
__device__ __forceinline__ uint32_t smem_u32(const void* p) {
    uint32_t a;
    asm("{ .reg .u64 t; cvta.to.shared.u64 t, %1; cvt.u32.u64 %0, t; }"
        : "=r"(a) : "l"(p));
    return a;
}
__device__ __forceinline__ void cp_async16(uint32_t dst, const void* src) {
    asm volatile("cp.async.cg.shared.global [%0], [%1], 16;"
                 :: "r"(dst), "l"(src) : "memory");
}
#define CP_COMMIT() asm volatile("cp.async.commit_group;" ::: "memory")
#define CP_WAIT(n)  asm volatile("cp.async.wait_group %0;" :: "n"(n) : "memory")

__device__ __forceinline__ void ldsm4(uint32_t* r, uint32_t addr) {
    asm volatile("ldmatrix.sync.aligned.m8n8.x4.shared.b16 {%0,%1,%2,%3}, [%4];"
                 : "=r"(r[0]), "=r"(r[1]), "=r"(r[2]), "=r"(r[3]) : "r"(addr));
}
__device__ __forceinline__ void ldsm2(uint32_t* r, uint32_t addr) {
    asm volatile("ldmatrix.sync.aligned.m8n8.x2.shared.b16 {%0,%1}, [%2];"
                 : "=r"(r[0]), "=r"(r[1]) : "r"(addr));
}
__device__ __forceinline__ void mma_bf16(float* d, const uint32_t* a, const uint32_t* b) {
    asm volatile(
        "mma.sync.aligned.m16n8k16.row.col.f32.bf16.bf16.f32 "
        "{%0,%1,%2,%3}, {%4,%5,%6,%7}, {%8,%9}, {%0,%1,%2,%3};"
        : "+f"(d[0]), "+f"(d[1]), "+f"(d[2]), "+f"(d[3])
        : "r"(a[0]), "r"(a[1]), "r"(a[2]), "r"(a[3]), "r"(b[0]), "r"(b[1]));
}

__device__ __forceinline__ float tanh_fast(float x) {
    float xc = fminf(fmaxf(x, -9.0f), 9.0f);
    float e = __expf(2.0f * xc);
    return (e - 1.0f) / (e + 1.0f);
}

// ---------------------------------------------------------------------------
// W1 transpose + bf16 hi/lo split
// ---------------------------------------------------------------------------
__global__ void w1split_kernel(const float* __restrict__ W1) {
    int k = blockIdx.x;
    int n = threadIdx.x;
    float x = W1[k * U_ + n];
    __nv_bfloat16 h = __float2bfloat16(x);
    __nv_bfloat16 l = __float2bfloat16(x - __bfloat162float(h));
    g_W1t_hi[n * D_ + k] = h;
    g_W1t_lo[n * D_ + k] = l;
}

// ---------------------------------------------------------------------------
// proj_q[b,u] = query[b,:] @ W2[:,u] + b2[u] + b1[u]
// ---------------------------------------------------------------------------
__global__ void projq_kernel(const float* __restrict__ query,
                             const float* __restrict__ W2,
                             const float* __restrict__ b1,
                             const float* __restrict__ b2) {
    __shared__ float q[D_];
    int b = blockIdx.x;
    for (int i = threadIdx.x; i < D_; i += blockDim.x) q[i] = query[b * D_ + i];
    __syncthreads();
    int u = threadIdx.x;
    float acc = b1[u] + b2[u];
#pragma unroll 8
    for (int d = 0; d < D_; d++) acc += q[d] * W2[d * U_ + u];
    g_projq[b * U_ + u] = acc;
}

// ---------------------------------------------------------------------------
// score kernel: split-bf16 mma.sync GEMM with SPLIT ACCUMULATORS
// ---------------------------------------------------------------------------
__global__ void __launch_bounds__(256, 1)
score_kernel(const float* __restrict__ values, const float* __restrict__ V) {
    extern __shared__ char smem[];
    const uint32_t sb = smem_u32(smem);
    const int tid = threadIdx.x;
    const int wid = tid >> 5;
    const int lane = tid & 31;
    const int wm = wid & 1;
    const int wn = wid >> 1;
    const int row0 = blockIdx.x * MT;
    const int b = row0 / T_;

    // ---- preload B chunk 0 ----
    {
#pragma unroll
        for (int it = 0; it < 4; it++) {
            int idx = tid + it * 256;
            int n = idx >> 4, c = idx & 15;
            uint32_t dst = sb + SM_B + n * B_STRIDE_B + c * 16;
            size_t goff = (size_t)n * D_ + c * 8;
            cp_async16(dst, g_W1t_hi + goff);
            cp_async16(dst + SM_B_LO, g_W1t_lo + goff);
        }
        CP_COMMIT();
    }

    // ---- stage pq + V ----
    {
        float* pqs = (float*)(smem + SM_PQ);
        float* Vs = (float*)(smem + SM_V);
        for (int i = tid; i < U_; i += 256) {
            pqs[i] = g_projq[b * U_ + i];
            Vs[i] = V[i];
        }
    }

    // ---- convert A (values[64 x 512]) fp32 -> bf16 hi/lo ----
    {
        const float4* src = (const float4*)(values + (size_t)row0 * D_);
#pragma unroll
        for (int it = 0; it < 32; it++) {
            int idx = tid + it * 256;
            int r = idx >> 7, c = idx & 127;
            float4 v = src[idx];
            __nv_bfloat16 h0 = __float2bfloat16(v.x);
            __nv_bfloat16 h1 = __float2bfloat16(v.y);
            __nv_bfloat16 h2 = __float2bfloat16(v.z);
            __nv_bfloat16 h3 = __float2bfloat16(v.w);
            __nv_bfloat16 l0 = __float2bfloat16(v.x - __bfloat162float(h0));
            __nv_bfloat16 l1 = __float2bfloat16(v.y - __bfloat162float(h1));
            __nv_bfloat16 l2 = __float2bfloat16(v.z - __bfloat162float(h2));
            __nv_bfloat16 l3 = __float2bfloat16(v.w - __bfloat162float(h3));
            uint32_t hp0 = ((uint32_t)__bfloat16_as_ushort(h1) << 16) | __bfloat16_as_ushort(h0);
            uint32_t hp1 = ((uint32_t)__bfloat16_as_ushort(h3) << 16) | __bfloat16_as_ushort(h2);
            uint32_t lp0 = ((uint32_t)__bfloat16_as_ushort(l1) << 16) | __bfloat16_as_ushort(l0);
            uint32_t lp1 = ((uint32_t)__bfloat16_as_ushort(l3) << 16) | __bfloat16_as_ushort(l2);
            uint32_t off = r * A_STRIDE_B + c * 8;
            *(uint2*)(smem + SM_A_HI + off) = make_uint2(hp0, hp1);
            *(uint2*)(smem + SM_A_LO + off) = make_uint2(lp0, lp1);
        }
    }

    // ---- ldmatrix lane bases ----
    const uint32_t a_lane = (uint32_t)(((lane & 7) + ((lane >> 3) & 1) * 8) * A_STRIDE_B
                                       + (lane >> 4) * 16);
    const uint32_t a_base = sb + SM_A_HI + (uint32_t)(wm * 32) * A_STRIDE_B + a_lane;
    const uint32_t b_lane = (uint32_t)((lane & 7) * B_STRIDE_B + ((lane >> 3) & 1) * 16);
    const uint32_t b_base = sb + SM_B + (uint32_t)(wn * 16) * B_STRIDE_B + b_lane;

    // split accumulators: hi = hi*hi products, mid = cross terms
    float acch[2][2][4], accm[2][2][4];
#pragma unroll
    for (int mf = 0; mf < 2; mf++)
#pragma unroll
        for (int nf = 0; nf < 2; nf++)
#pragma unroll
            for (int j = 0; j < 4; j++) { acch[mf][nf][j] = 0.f; accm[mf][nf][j] = 0.f; }
    float sp[4] = {0.f, 0.f, 0.f, 0.f};

    const float* pqs = (const float*)(smem + SM_PQ);
    const float* Vs = (const float*)(smem + SM_V);

    for (int i = 0; i < 32; i++) {              // nt = i>>2, kc = i&3
        const int nt = i >> 2;
        const int kc = i & 3;
        const int buf = i & 1;

        if (i + 1 < 32) {
            const int nn = (i + 1) >> 2, nk = (i + 1) & 3, nb = (i + 1) & 1;
#pragma unroll
            for (int it = 0; it < 4; it++) {
                int idx = tid + it * 256;
                int n = idx >> 4, c = idx & 15;
                uint32_t dst = sb + SM_B + nb * SM_B_BUF + n * B_STRIDE_B + c * 16;
                size_t goff = (size_t)(nn * NTILE + n) * D_ + nk * KCH + c * 8;
                cp_async16(dst, g_W1t_hi + goff);
                cp_async16(dst + SM_B_LO, g_W1t_lo + goff);
            }
            CP_COMMIT();
            CP_WAIT(1);
        } else {
            CP_WAIT(0);
        }
        __syncthreads();

        const uint32_t ab = a_base + (uint32_t)kc * 256;
        const uint32_t bb = b_base + (uint32_t)buf * SM_B_BUF;
#pragma unroll
        for (int ks = 0; ks < 8; ks++) {
            uint32_t ah[2][4], al[2][4], bh[2][2], bl[2][2];
            ldsm4(ah[0], ab + ks * 32);
            ldsm4(ah[1], ab + 16 * A_STRIDE_B + ks * 32);
            ldsm4(al[0], ab + SM_A_LO + ks * 32);
            ldsm4(al[1], ab + SM_A_LO + 16 * A_STRIDE_B + ks * 32);
            ldsm2(bh[0], bb + ks * 32);
            ldsm2(bh[1], bb + 8 * B_STRIDE_B + ks * 32);
            ldsm2(bl[0], bb + SM_B_LO + ks * 32);
            ldsm2(bl[1], bb + SM_B_LO + 8 * B_STRIDE_B + ks * 32);
            // 4 independent hi*hi chains first...
#pragma unroll
            for (int mf = 0; mf < 2; mf++)
#pragma unroll
                for (int nf = 0; nf < 2; nf++)
                    mma_bf16(acch[mf][nf], ah[mf], bh[nf]);
            // ...then 8 cross-term MMAs into the separate mid accumulators
#pragma unroll
            for (int mf = 0; mf < 2; mf++)
#pragma unroll
                for (int nf = 0; nf < 2; nf++) {
                    mma_bf16(accm[mf][nf], ah[mf], bl[nf]);
                    mma_bf16(accm[mf][nf], al[mf], bh[nf]);
                }
        }

        if (kc == 3) {
            // ---- epilogue for N-tile nt ----
#pragma unroll
            for (int mf = 0; mf < 2; mf++)
#pragma unroll
                for (int nf = 0; nf < 2; nf++) {
                    int u0 = nt * NTILE + wn * 16 + nf * 8 + (lane & 3) * 2;
                    float pq0 = pqs[u0], pq1 = pqs[u0 + 1];
                    float v0 = Vs[u0], v1 = Vs[u0 + 1];
                    float p0 = acch[mf][nf][0] + accm[mf][nf][0] + pq0;
                    float p1 = acch[mf][nf][1] + accm[mf][nf][1] + pq1;
                    float p2 = acch[mf][nf][2] + accm[mf][nf][2] + pq0;
                    float p3 = acch[mf][nf][3] + accm[mf][nf][3] + pq1;
                    sp[mf * 2 + 0] += tanh_fast(p0) * v0 + tanh_fast(p1) * v1;
                    sp[mf * 2 + 1] += tanh_fast(p2) * v0 + tanh_fast(p3) * v1;
#pragma unroll
                    for (int j = 0; j < 4; j++) { acch[mf][nf][j] = 0.f; accm[mf][nf][j] = 0.f; }
                }
        }
        __syncthreads();
    }

    // ---- reduce score partials ----
#pragma unroll
    for (int j = 0; j < 4; j++) {
        sp[j] += __shfl_xor_sync(0xffffffffu, sp[j], 1);
        sp[j] += __shfl_xor_sync(0xffffffffu, sp[j], 2);
    }
    float* red = (float*)(smem + SM_RED);
    if ((lane & 3) == 0) {
        int g = lane >> 2;
#pragma unroll
        for (int mf = 0; mf < 2; mf++) {
            int r0 = wm * 32 + mf * 16 + g;
            red[r0 * 4 + wn] = sp[mf * 2 + 0];
            red[(r0 + 8) * 4 + wn] = sp[mf * 2 + 1];
        }
    }
    __syncthreads();
    if (tid < MT) {
        g_score[row0 + tid] = red[tid * 4] + red[tid * 4 + 1]
                            + red[tid * 4 + 2] + red[tid * 4 + 3];
    }
}

// ---------------------------------------------------------------------------
// softmax over T per batch -> weights; zero context region
// ---------------------------------------------------------------------------
__global__ void softmax_kernel(float* __restrict__ out) {
    __shared__ float sdata[256];
    const int b = blockIdx.x, tid = threadIdx.x;
    float s[8];
    float mx = -1e30f;
#pragma unroll
    for (int i = 0; i < 8; i++) {
        s[i] = g_score[b * T_ + tid + i * 256];
        mx = fmaxf(mx, s[i]);
    }
    sdata[tid] = mx;
    __syncthreads();
    for (int off = 128; off > 0; off >>= 1) {
        if (tid < off) sdata[tid] = fmaxf(sdata[tid], sdata[tid + off]);
        __syncthreads();
    }
    mx = sdata[0];
    __syncthreads();
    float sum = 0.f;
#pragma unroll
    for (int i = 0; i < 8; i++) {
        s[i] = __expf(s[i] - mx);
        sum += s[i];
    }
    sdata[tid] = sum;
    __syncthreads();
    for (int off = 128; off > 0; off >>= 1) {
        if (tid < off) sdata[tid] += sdata[tid + off];
        __syncthreads();
    }
    float inv = 1.0f / sdata[0];
    float* w = out + B_ * D_;
#pragma unroll
    for (int i = 0; i < 8; i++) w[b * T_ + tid + i * 256] = s[i] * inv;

    out[b * D_ + tid] = 0.f;
    out[b * D_ + 256 + tid] = 0.f;
}

// ---------------------------------------------------------------------------
// context[b,d] = sum_t w[b,t] * values[b,t,d]
// ---------------------------------------------------------------------------
__global__ void __launch_bounds__(128)
context_kernel(const float* __restrict__ values, float* __restrict__ out) {
    const int b = blockIdx.x;
    const int t0 = blockIdx.y * 128;
    const int tid = threadIdx.x;
    __shared__ float ws[128];
    ws[tid] = out[B_ * D_ + b * T_ + t0 + tid];
    __syncthreads();
    const float4* vp = (const float4*)(values + ((size_t)b * T_ + t0) * D_) + tid;
    float ax = 0.f, ay = 0.f, az = 0.f, aw = 0.f;
#pragma unroll 4
    for (int tt = 0; tt < 128; tt++) {
        float w = ws[tt];
        float4 v = vp[tt * 128];
        ax += w * v.x; ay += w * v.y; az += w * v.z; aw += w * v.w;
    }
    float* o = out + b * D_ + tid * 4;
    atomicAdd(o + 0, ax);
    atomicAdd(o + 1, ay);
    atomicAdd(o + 2, az);
    atomicAdd(o + 3, aw);
}

// ---------------------------------------------------------------------------
extern "C" void kernel_launch(void* const* d_in, const int* in_sizes, int n_in,
                              void* d_out, int out_size) {
    const float* values = (const float*)d_in[0];
    const float* query  = (const float*)d_in[1];
    const float* W1     = (const float*)d_in[2];
    const float* b1     = (const float*)d_in[3];
    const float* W2     = (const float*)d_in[4];
    const float* b2     = (const float*)d_in[5];
    const float* V      = (const float*)d_in[6];
    // d_in[7] = bV: softmax shift-invariant -> unused
    float* out = (float*)d_out;

    cudaFuncSetAttribute(score_kernel,
                         cudaFuncAttributeMaxDynamicSharedMemorySize, SMEM_TOTAL);

    w1split_kernel<<<D_, U_>>>(W1);
    projq_kernel<<<B_, U_>>>(query, W2, b1, b2);
    score_kernel<<<(B_ * T_) / MT, 256, SMEM_TOTAL>>>(values, V);
    softmax_kernel<<<B_, 256>>>(out);
    context_kernel<<<dim3(B_, 16), 128>>>(values, out);
}

// round 7
// speedup vs baseline: 2.1212x; 1.2470x over previous
#include <cuda_runtime.h>
#include <cuda_fp16.h>
#include <math.h>
#include <stdint.h>

#define B_ 32
#define T_ 2048
#define D_ 512
#define U_ 512

// ---------------------------------------------------------------------------
// score tiling (R3 shape): CTA = 64 rows x full U, 8 warps 2(M) x 4(N),
// warp tile 32x16, N-tiles of 64 u, B chunks k=128 double-buffered.
// A: single fp16 limb. B: two fp16 limbs (hi+lo of W1).
// ---------------------------------------------------------------------------
#define MT 64
#define NTILE 64
#define KCH 128
#define A_STRIDE_B 1040       // 520 fp16 per row; %128==16 -> conflict-free ldsm
#define B_STRIDE_B 272        // 136 fp16 per row

// smem byte offsets
#define SM_A      0                       // 64*1040 = 66560
#define SM_B      66560                   // 2 bufs x (hi 17408 + lo 17408)
#define SM_B_BUF  34816
#define SM_B_LO   17408
#define SM_PQ     136192
#define SM_V      138240
#define SM_RED    140288
#define SMEM_TOTAL 141312

// ---------------------------------------------------------------------------
// scratch globals
// ---------------------------------------------------------------------------
__device__ float g_projq[B_ * U_];
__device__ float g_score[B_ * T_];
__device__ __align__(16) __half g_W1t_hi[U_ * D_];  // [n][k]
__device__ __align__(16) __half g_W1t_lo[U_ * D_];

// ---------------------------------------------------------------------------
// PTX helpers (sm_80+ only; harness targets compute_103 -> no 'a' features)
// ---------------------------------------------------------------------------
__device__ __forceinline__ uint32_t smem_u32(const void* p) {
    uint32_t a;
    asm("{ .reg .u64 t; cvta.to.shared.u64 t, %1; cvt.u32.u64 %0, t; }"
        : "=r"(a) : "l"(p));
    return a;
}
__device__ __forceinline__ void cp_async16(uint32_t dst, const void* src) {
    asm volatile("cp.async.cg.shared.global [%0], [%1], 16;"
                 :: "r"(dst), "l"(src) : "memory");
}
#define CP_COMMIT() asm volatile("cp.async.commit_group;" ::: "memory")
#define CP_WAIT(n)  asm volatile("cp.async.wait_group %0;" :: "n"(n) : "memory")

__device__ __forceinline__ void ldsm4(uint32_t* r, uint32_t addr) {
    asm volatile("ldmatrix.sync.aligned.m8n8.x4.shared.b16 {%0,%1,%2,%3}, [%4];"
                 : "=r"(r[0]), "=r"(r[1]), "=r"(r[2]), "=r"(r[3]) : "r"(addr));
}
__device__ __forceinline__ void ldsm2(uint32_t* r, uint32_t addr) {
    asm volatile("ldmatrix.sync.aligned.m8n8.x2.shared.b16 {%0,%1}, [%2];"
                 : "=r"(r[0]), "=r"(r[1]) : "r"(addr));
}
__device__ __forceinline__ void mma_f16(float* d, const uint32_t* a, const uint32_t* b) {
    asm volatile(
        "mma.sync.aligned.m16n8k16.row.col.f32.f16.f16.f32 "
        "{%0,%1,%2,%3}, {%4,%5,%6,%7}, {%8,%9}, {%0,%1,%2,%3};"
        : "+f"(d[0]), "+f"(d[1]), "+f"(d[2]), "+f"(d[3])
        : "r"(a[0]), "r"(a[1]), "r"(a[2]), "r"(a[3]), "r"(b[0]), "r"(b[1]));
}

__device__ __forceinline__ float tanh_fast(float x) {
    float xc = fminf(fmaxf(x, -9.0f), 9.0f);
    float e = __expf(2.0f * xc);
    return (e - 1.0f) / (e + 1.0f);
}

// ---------------------------------------------------------------------------
// W1 transpose + fp16 hi/lo split:  W1[k][n] -> W1t_{hi,lo}[n][k]
// ---------------------------------------------------------------------------
__global__ void w1split_kernel(const float* __restrict__ W1) {
    int k = blockIdx.x;
    int n = threadIdx.x;
    float x = W1[k * U_ + n];
    __half h = __float2half_rn(x);
    __half l = __float2half_rn(x - __half2float(h));
    g_W1t_hi[n * D_ + k] = h;
    g_W1t_lo[n * D_ + k] = l;
}

// ---------------------------------------------------------------------------
// proj_q[b,u] = query[b,:] @ W2[:,u] + b2[u] + b1[u]
// ---------------------------------------------------------------------------
__global__ void projq_kernel(const float* __restrict__ query,
                             const float* __restrict__ W2,
                             const float* __restrict__ b1,
                             const float* __restrict__ b2) {
    __shared__ float q[D_];
    int b = blockIdx.x;
    for (int i = threadIdx.x; i < D_; i += blockDim.x) q[i] = query[b * D_ + i];
    __syncthreads();
    int u = threadIdx.x;
    float acc = b1[u] + b2[u];
#pragma unroll 8
    for (int d = 0; d < D_; d++) acc += q[d] * W2[d * U_ + u];
    g_projq[b * U_ + u] = acc;
}

// ---------------------------------------------------------------------------
// score kernel: 2-term fp16 mma.sync GEMM (ah*bh + ah*bl) + fused tanh/V epilogue
// ---------------------------------------------------------------------------
__global__ void __launch_bounds__(256, 1)
score_kernel(const float* __restrict__ values, const float* __restrict__ V) {
    extern __shared__ char smem[];
    const uint32_t sb = smem_u32(smem);
    const int tid = threadIdx.x;
    const int wid = tid >> 5;
    const int lane = tid & 31;
    const int wm = wid & 1;
    const int wn = wid >> 1;
    const int row0 = blockIdx.x * MT;
    const int b = row0 / T_;

    // ---- preload B chunk 0 ----
    {
#pragma unroll
        for (int it = 0; it < 4; it++) {
            int idx = tid + it * 256;
            int n = idx >> 4, c = idx & 15;
            uint32_t dst = sb + SM_B + n * B_STRIDE_B + c * 16;
            size_t goff = (size_t)n * D_ + c * 8;
            cp_async16(dst, g_W1t_hi + goff);
            cp_async16(dst + SM_B_LO, g_W1t_lo + goff);
        }
        CP_COMMIT();
    }

    // ---- stage pq + V ----
    {
        float* pqs = (float*)(smem + SM_PQ);
        float* Vs = (float*)(smem + SM_V);
        for (int i = tid; i < U_; i += 256) {
            pqs[i] = g_projq[b * U_ + i];
            Vs[i] = V[i];
        }
    }

    // ---- convert A (values[64 x 512]) fp32 -> fp16 single limb ----
    {
        const float4* src = (const float4*)(values + (size_t)row0 * D_);
#pragma unroll
        for (int it = 0; it < 32; it++) {
            int idx = tid + it * 256;           // 8192 float4
            int r = idx >> 7, c = idx & 127;
            float4 v = src[idx];
            __half2 p0 = __floats2half2_rn(v.x, v.y);
            __half2 p1 = __floats2half2_rn(v.z, v.w);
            uint32_t off = r * A_STRIDE_B + c * 8;
            *(__half2*)(smem + SM_A + off) = p0;
            *(__half2*)(smem + SM_A + off + 4) = p1;
        }
    }

    // ---- ldmatrix lane bases ----
    const uint32_t a_lane = (uint32_t)(((lane & 7) + ((lane >> 3) & 1) * 8) * A_STRIDE_B
                                       + (lane >> 4) * 16);
    const uint32_t a_base = sb + SM_A + (uint32_t)(wm * 32) * A_STRIDE_B + a_lane;
    const uint32_t b_lane = (uint32_t)((lane & 7) * B_STRIDE_B + ((lane >> 3) & 1) * 16);
    const uint32_t b_base = sb + SM_B + (uint32_t)(wn * 16) * B_STRIDE_B + b_lane;

    float acc[2][2][4];
#pragma unroll
    for (int mf = 0; mf < 2; mf++)
#pragma unroll
        for (int nf = 0; nf < 2; nf++)
#pragma unroll
            for (int j = 0; j < 4; j++) acc[mf][nf][j] = 0.f;
    float sp[4] = {0.f, 0.f, 0.f, 0.f};

    const float* pqs = (const float*)(smem + SM_PQ);
    const float* Vs = (const float*)(smem + SM_V);

    for (int i = 0; i < 32; i++) {              // nt = i>>2, kc = i&3
        const int nt = i >> 2;
        const int kc = i & 3;
        const int buf = i & 1;

        if (i + 1 < 32) {                       // prefetch next B chunk
            const int nn = (i + 1) >> 2, nk = (i + 1) & 3, nb = (i + 1) & 1;
#pragma unroll
            for (int it = 0; it < 4; it++) {
                int idx = tid + it * 256;
                int n = idx >> 4, c = idx & 15;
                uint32_t dst = sb + SM_B + nb * SM_B_BUF + n * B_STRIDE_B + c * 16;
                size_t goff = (size_t)(nn * NTILE + n) * D_ + nk * KCH + c * 8;
                cp_async16(dst, g_W1t_hi + goff);
                cp_async16(dst + SM_B_LO, g_W1t_lo + goff);
            }
            CP_COMMIT();
            CP_WAIT(1);
        } else {
            CP_WAIT(0);
        }
        __syncthreads();

        const uint32_t ab = a_base + (uint32_t)kc * 256;    // 128 k-els * 2B
        const uint32_t bb = b_base + (uint32_t)buf * SM_B_BUF;
#pragma unroll
        for (int ks = 0; ks < 8; ks++) {
            uint32_t ah[2][4], bh[2][2], bl[2][2];
            ldsm4(ah[0], ab + ks * 32);
            ldsm4(ah[1], ab + 16 * A_STRIDE_B + ks * 32);
            ldsm2(bh[0], bb + ks * 32);
            ldsm2(bh[1], bb + 8 * B_STRIDE_B + ks * 32);
            ldsm2(bl[0], bb + SM_B_LO + ks * 32);
            ldsm2(bl[1], bb + SM_B_LO + 8 * B_STRIDE_B + ks * 32);
#pragma unroll
            for (int mf = 0; mf < 2; mf++)
#pragma unroll
                for (int nf = 0; nf < 2; nf++) {
                    mma_f16(acc[mf][nf], ah[mf], bh[nf]);
                    mma_f16(acc[mf][nf], ah[mf], bl[nf]);
                }
        }

        if (kc == 3) {
            // ---- epilogue for N-tile nt ----
#pragma unroll
            for (int mf = 0; mf < 2; mf++)
#pragma unroll
                for (int nf = 0; nf < 2; nf++) {
                    int u0 = nt * NTILE + wn * 16 + nf * 8 + (lane & 3) * 2;
                    float pq0 = pqs[u0], pq1 = pqs[u0 + 1];
                    float v0 = Vs[u0], v1 = Vs[u0 + 1];
                    sp[mf * 2 + 0] += tanh_fast(acc[mf][nf][0] + pq0) * v0
                                    + tanh_fast(acc[mf][nf][1] + pq1) * v1;
                    sp[mf * 2 + 1] += tanh_fast(acc[mf][nf][2] + pq0) * v0
                                    + tanh_fast(acc[mf][nf][3] + pq1) * v1;
#pragma unroll
                    for (int j = 0; j < 4; j++) acc[mf][nf][j] = 0.f;
                }
        }
        __syncthreads();
    }

    // ---- reduce score partials ----
#pragma unroll
    for (int j = 0; j < 4; j++) {
        sp[j] += __shfl_xor_sync(0xffffffffu, sp[j], 1);
        sp[j] += __shfl_xor_sync(0xffffffffu, sp[j], 2);
    }
    float* red = (float*)(smem + SM_RED);
    if ((lane & 3) == 0) {
        int g = lane >> 2;
#pragma unroll
        for (int mf = 0; mf < 2; mf++) {
            int r0 = wm * 32 + mf * 16 + g;
            red[r0 * 4 + wn] = sp[mf * 2 + 0];
            red[(r0 + 8) * 4 + wn] = sp[mf * 2 + 1];
        }
    }
    __syncthreads();
    if (tid < MT) {
        g_score[row0 + tid] = red[tid * 4] + red[tid * 4 + 1]
                            + red[tid * 4 + 2] + red[tid * 4 + 3];
    }
}

// ---------------------------------------------------------------------------
// softmax over T per batch -> weights; zero context region
// ---------------------------------------------------------------------------
__global__ void softmax_kernel(float* __restrict__ out) {
    __shared__ float sdata[256];
    const int b = blockIdx.x, tid = threadIdx.x;
    float s[8];
    float mx = -1e30f;
#pragma unroll
    for (int i = 0; i < 8; i++) {
        s[i] = g_score[b * T_ + tid + i * 256];
        mx = fmaxf(mx, s[i]);
    }
    sdata[tid] = mx;
    __syncthreads();
    for (int off = 128; off > 0; off >>= 1) {
        if (tid < off) sdata[tid] = fmaxf(sdata[tid], sdata[tid + off]);
        __syncthreads();
    }
    mx = sdata[0];
    __syncthreads();
    float sum = 0.f;
#pragma unroll
    for (int i = 0; i < 8; i++) {
        s[i] = __expf(s[i] - mx);
        sum += s[i];
    }
    sdata[tid] = sum;
    __syncthreads();
    for (int off = 128; off > 0; off >>= 1) {
        if (tid < off) sdata[tid] += sdata[tid + off];
        __syncthreads();
    }
    float inv = 1.0f / sdata[0];
    float* w = out + B_ * D_;
#pragma unroll
    for (int i = 0; i < 8; i++) w[b * T_ + tid + i * 256] = s[i] * inv;

    out[b * D_ + tid] = 0.f;
    out[b * D_ + 256 + tid] = 0.f;
}

// ---------------------------------------------------------------------------
// context[b,d] = sum_t w[b,t] * values[b,t,d]
// ---------------------------------------------------------------------------
__global__ void __launch_bounds__(128)
context_kernel(const float* __restrict__ values, float* __restrict__ out) {
    const int b = blockIdx.x;
    const int t0 = blockIdx.y * 128;
    const int tid = threadIdx.x;
    __shared__ float ws[128];
    ws[tid] = out[B_ * D_ + b * T_ + t0 + tid];
    __syncthreads();
    const float4* vp = (const float4*)(values + ((size_t)b * T_ + t0) * D_) + tid;
    float ax = 0.f, ay = 0.f, az = 0.f, aw = 0.f;
#pragma unroll 4
    for (int tt = 0; tt < 128; tt++) {
        float w = ws[tt];
        float4 v = vp[tt * 128];
        ax += w * v.x; ay += w * v.y; az += w * v.z; aw += w * v.w;
    }
    float* o = out + b * D_ + tid * 4;
    atomicAdd(o + 0, ax);
    atomicAdd(o + 1, ay);
    atomicAdd(o + 2, az);
    atomicAdd(o + 3, aw);
}

// ---------------------------------------------------------------------------
extern "C" void kernel_launch(void* const* d_in, const int* in_sizes, int n_in,
                              void* d_out, int out_size) {
    const float* values = (const float*)d_in[0];
    const float* query  = (const float*)d_in[1];
    const float* W1     = (const float*)d_in[2];
    const float* b1     = (const float*)d_in[3];
    const float* W2     = (const float*)d_in[4];
    const float* b2     = (const float*)d_in[5];
    const float* V      = (const float*)d_in[6];
    // d_in[7] = bV: softmax shift-invariant -> unused
    float* out = (float*)d_out;

    cudaFuncSetAttribute(score_kernel,
                         cudaFuncAttributeMaxDynamicSharedMemorySize, SMEM_TOTAL);

    w1split_kernel<<<D_, U_>>>(W1);
    projq_kernel<<<B_, U_>>>(query, W2, b1, b2);
    score_kernel<<<(B_ * T_) / MT, 256, SMEM_TOTAL>>>(values, V);
    softmax_kernel<<<B_, 256>>>(out);
    context_kernel<<<dim3(B_, 16), 128>>>(values, out);
}

// round 8
// speedup vs baseline: 3.3752x; 1.5911x over previous
#include <cuda_runtime.h>
#include <cuda_fp16.h>
#include <math.h>
#include <stdint.h>

#define B_ 32
#define T_ 2048
#define D_ 512
#define U_ 512

// ---------------------------------------------------------------------------
// score tiling: CTA = 64 rows x full U, 8 warps 2(M) x 4(N), warp tile 32x16,
// N-tiles of 64 u, B chunks k=128 double-buffered. Plain fp16 single MMA.
// ---------------------------------------------------------------------------
#define MT 64
#define NTILE 64
#define KCH 128
#define A_STRIDE_B 1040       // 520 fp16 per row; %128==16 -> conflict-free ldsm
#define B_STRIDE_B 272        // 136 fp16 per row

// smem byte offsets
#define SM_A      0                       // 64*1040 = 66560
#define SM_B      66560                   // 2 bufs x 17408
#define SM_B_BUF  17408
#define SM_PQ     101376
#define SM_V      103424
#define SM_RED    105472
#define SMEM_TOTAL 106496

// ---------------------------------------------------------------------------
// scratch globals
// ---------------------------------------------------------------------------
__device__ float g_projq[B_ * U_];
__device__ float g_score[B_ * T_];
__device__ __align__(16) __half g_W1t[U_ * D_];   // [n][k] fp16

// ---------------------------------------------------------------------------
// PTX helpers (sm_80+ only; harness targets compute_103 -> no 'a' features)
// ---------------------------------------------------------------------------
__device__ __forceinline__ uint32_t smem_u32(const void* p) {
    uint32_t a;
    asm("{ .reg .u64 t; cvta.to.shared.u64 t, %1; cvt.u32.u64 %0, t; }"
        : "=r"(a) : "l"(p));
    return a;
}
__device__ __forceinline__ void cp_async16(uint32_t dst, const void* src) {
    asm volatile("cp.async.cg.shared.global [%0], [%1], 16;"
                 :: "r"(dst), "l"(src) : "memory");
}
#define CP_COMMIT() asm volatile("cp.async.commit_group;" ::: "memory")
#define CP_WAIT(n)  asm volatile("cp.async.wait_group %0;" :: "n"(n) : "memory")

__device__ __forceinline__ void ldsm4(uint32_t* r, uint32_t addr) {
    asm volatile("ldmatrix.sync.aligned.m8n8.x4.shared.b16 {%0,%1,%2,%3}, [%4];"
                 : "=r"(r[0]), "=r"(r[1]), "=r"(r[2]), "=r"(r[3]) : "r"(addr));
}
__device__ __forceinline__ void ldsm2(uint32_t* r, uint32_t addr) {
    asm volatile("ldmatrix.sync.aligned.m8n8.x2.shared.b16 {%0,%1}, [%2];"
                 : "=r"(r[0]), "=r"(r[1]) : "r"(addr));
}
__device__ __forceinline__ void mma_f16(float* d, const uint32_t* a, const uint32_t* b) {
    asm volatile(
        "mma.sync.aligned.m16n8k16.row.col.f32.f16.f16.f32 "
        "{%0,%1,%2,%3}, {%4,%5,%6,%7}, {%8,%9}, {%0,%1,%2,%3};"
        : "+f"(d[0]), "+f"(d[1]), "+f"(d[2]), "+f"(d[3])
        : "r"(a[0]), "r"(a[1]), "r"(a[2]), "r"(a[3]), "r"(b[0]), "r"(b[1]));
}

__device__ __forceinline__ float tanh_fast(float x) {
    float xc = fminf(fmaxf(x, -9.0f), 9.0f);
    float e = __expf(2.0f * xc);
    return (e - 1.0f) / (e + 1.0f);
}

// ---------------------------------------------------------------------------
// W1 transpose to fp16:  W1[k][n] -> W1t[n][k]
// ---------------------------------------------------------------------------
__global__ void w1cvt_kernel(const float* __restrict__ W1) {
    int k = blockIdx.x;
    int n = threadIdx.x;
    g_W1t[n * D_ + k] = __float2half_rn(W1[k * U_ + n]);
}

// ---------------------------------------------------------------------------
// proj_q[b,u] = query[b,:] @ W2[:,u] + b2[u] + b1[u]
// ---------------------------------------------------------------------------
__global__ void projq_kernel(const float* __restrict__ query,
                             const float* __restrict__ W2,
                             const float* __restrict__ b1,
                             const float* __restrict__ b2) {
    __shared__ float q[D_];
    int b = blockIdx.x;
    for (int i = threadIdx.x; i < D_; i += blockDim.x) q[i] = query[b * D_ + i];
    __syncthreads();
    int u = threadIdx.x;
    float acc = b1[u] + b2[u];
#pragma unroll 8
    for (int d = 0; d < D_; d++) acc += q[d] * W2[d * U_ + u];
    g_projq[b * U_ + u] = acc;
}

// ---------------------------------------------------------------------------
// score kernel: fp16 mma.sync GEMM + fused tanh/V epilogue
// ---------------------------------------------------------------------------
__global__ void __launch_bounds__(256, 2)
score_kernel(const float* __restrict__ values, const float* __restrict__ V) {
    extern __shared__ char smem[];
    const uint32_t sb = smem_u32(smem);
    const int tid = threadIdx.x;
    const int wid = tid >> 5;
    const int lane = tid & 31;
    const int wm = wid & 1;
    const int wn = wid >> 1;
    const int row0 = blockIdx.x * MT;
    const int b = row0 / T_;

    // ---- preload B chunk 0 ----
    {
#pragma unroll
        for (int it = 0; it < 4; it++) {
            int idx = tid + it * 256;           // 1024 16B chunks
            int n = idx >> 4, c = idx & 15;
            uint32_t dst = sb + SM_B + n * B_STRIDE_B + c * 16;
            cp_async16(dst, g_W1t + (size_t)n * D_ + c * 8);
        }
        CP_COMMIT();
    }

    // ---- stage pq + V ----
    {
        float* pqs = (float*)(smem + SM_PQ);
        float* Vs = (float*)(smem + SM_V);
        for (int i = tid; i < U_; i += 256) {
            pqs[i] = g_projq[b * U_ + i];
            Vs[i] = V[i];
        }
    }

    // ---- convert A (values[64 x 512]) fp32 -> fp16 in smem ----
    {
        const float4* src = (const float4*)(values + (size_t)row0 * D_);
#pragma unroll
        for (int it = 0; it < 32; it++) {
            int idx = tid + it * 256;           // 8192 float4
            int r = idx >> 7, c = idx & 127;
            float4 v = src[idx];
            __half2 p0 = __floats2half2_rn(v.x, v.y);
            __half2 p1 = __floats2half2_rn(v.z, v.w);
            uint32_t off = r * A_STRIDE_B + c * 8;
            *(__half2*)(smem + SM_A + off) = p0;
            *(__half2*)(smem + SM_A + off + 4) = p1;
        }
    }

    // ---- ldmatrix lane bases ----
    const uint32_t a_lane = (uint32_t)(((lane & 7) + ((lane >> 3) & 1) * 8) * A_STRIDE_B
                                       + (lane >> 4) * 16);
    const uint32_t a_base = sb + SM_A + (uint32_t)(wm * 32) * A_STRIDE_B + a_lane;
    const uint32_t b_lane = (uint32_t)((lane & 7) * B_STRIDE_B + ((lane >> 3) & 1) * 16);
    const uint32_t b_base = sb + SM_B + (uint32_t)(wn * 16) * B_STRIDE_B + b_lane;

    float acc[2][2][4];
#pragma unroll
    for (int mf = 0; mf < 2; mf++)
#pragma unroll
        for (int nf = 0; nf < 2; nf++)
#pragma unroll
            for (int j = 0; j < 4; j++) acc[mf][nf][j] = 0.f;
    float sp[4] = {0.f, 0.f, 0.f, 0.f};

    const float* pqs = (const float*)(smem + SM_PQ);
    const float* Vs = (const float*)(smem + SM_V);

    for (int i = 0; i < 32; i++) {              // nt = i>>2, kc = i&3
        const int nt = i >> 2;
        const int kc = i & 3;
        const int buf = i & 1;

        if (i + 1 < 32) {                       // prefetch next B chunk
            const int nn = (i + 1) >> 2, nk = (i + 1) & 3, nb = (i + 1) & 1;
#pragma unroll
            for (int it = 0; it < 4; it++) {
                int idx = tid + it * 256;
                int n = idx >> 4, c = idx & 15;
                uint32_t dst = sb + SM_B + nb * SM_B_BUF + n * B_STRIDE_B + c * 16;
                cp_async16(dst, g_W1t + (size_t)(nn * NTILE + n) * D_ + nk * KCH + c * 8);
            }
            CP_COMMIT();
            CP_WAIT(1);
        } else {
            CP_WAIT(0);
        }
        __syncthreads();

        const uint32_t ab = a_base + (uint32_t)kc * 256;
        const uint32_t bb = b_base + (uint32_t)buf * SM_B_BUF;
#pragma unroll
        for (int ks = 0; ks < 8; ks++) {
            uint32_t ah[2][4], bh[2][2];
            ldsm4(ah[0], ab + ks * 32);
            ldsm4(ah[1], ab + 16 * A_STRIDE_B + ks * 32);
            ldsm2(bh[0], bb + ks * 32);
            ldsm2(bh[1], bb + 8 * B_STRIDE_B + ks * 32);
#pragma unroll
            for (int mf = 0; mf < 2; mf++)
#pragma unroll
                for (int nf = 0; nf < 2; nf++)
                    mma_f16(acc[mf][nf], ah[mf], bh[nf]);
        }

        if (kc == 3) {
            // ---- epilogue for N-tile nt ----
#pragma unroll
            for (int mf = 0; mf < 2; mf++)
#pragma unroll
                for (int nf = 0; nf < 2; nf++) {
                    int u0 = nt * NTILE + wn * 16 + nf * 8 + (lane & 3) * 2;
                    float pq0 = pqs[u0], pq1 = pqs[u0 + 1];
                    float v0 = Vs[u0], v1 = Vs[u0 + 1];
                    sp[mf * 2 + 0] += tanh_fast(acc[mf][nf][0] + pq0) * v0
                                    + tanh_fast(acc[mf][nf][1] + pq1) * v1;
                    sp[mf * 2 + 1] += tanh_fast(acc[mf][nf][2] + pq0) * v0
                                    + tanh_fast(acc[mf][nf][3] + pq1) * v1;
#pragma unroll
                    for (int j = 0; j < 4; j++) acc[mf][nf][j] = 0.f;
                }
        }
        __syncthreads();
    }

    // ---- reduce score partials ----
#pragma unroll
    for (int j = 0; j < 4; j++) {
        sp[j] += __shfl_xor_sync(0xffffffffu, sp[j], 1);
        sp[j] += __shfl_xor_sync(0xffffffffu, sp[j], 2);
    }
    float* red = (float*)(smem + SM_RED);
    if ((lane & 3) == 0) {
        int g = lane >> 2;
#pragma unroll
        for (int mf = 0; mf < 2; mf++) {
            int r0 = wm * 32 + mf * 16 + g;
            red[r0 * 4 + wn] = sp[mf * 2 + 0];
            red[(r0 + 8) * 4 + wn] = sp[mf * 2 + 1];
        }
    }
    __syncthreads();
    if (tid < MT) {
        g_score[row0 + tid] = red[tid * 4] + red[tid * 4 + 1]
                            + red[tid * 4 + 2] + red[tid * 4 + 3];
    }
}

// ---------------------------------------------------------------------------
// softmax over T per batch -> weights; zero context region
// ---------------------------------------------------------------------------
__global__ void softmax_kernel(float* __restrict__ out) {
    __shared__ float sdata[256];
    const int b = blockIdx.x, tid = threadIdx.x;
    float s[8];
    float mx = -1e30f;
#pragma unroll
    for (int i = 0; i < 8; i++) {
        s[i] = g_score[b * T_ + tid + i * 256];
        mx = fmaxf(mx, s[i]);
    }
    sdata[tid] = mx;
    __syncthreads();
    for (int off = 128; off > 0; off >>= 1) {
        if (tid < off) sdata[tid] = fmaxf(sdata[tid], sdata[tid + off]);
        __syncthreads();
    }
    mx = sdata[0];
    __syncthreads();
    float sum = 0.f;
#pragma unroll
    for (int i = 0; i < 8; i++) {
        s[i] = __expf(s[i] - mx);
        sum += s[i];
    }
    sdata[tid] = sum;
    __syncthreads();
    for (int off = 128; off > 0; off >>= 1) {
        if (tid < off) sdata[tid] += sdata[tid + off];
        __syncthreads();
    }
    float inv = 1.0f / sdata[0];
    float* w = out + B_ * D_;
#pragma unroll
    for (int i = 0; i < 8; i++) w[b * T_ + tid + i * 256] = s[i] * inv;

    out[b * D_ + tid] = 0.f;
    out[b * D_ + 256 + tid] = 0.f;
}

// ---------------------------------------------------------------------------
// context[b,d] = sum_t w[b,t] * values[b,t,d]
// ---------------------------------------------------------------------------
__global__ void __launch_bounds__(128)
context_kernel(const float* __restrict__ values, float* __restrict__ out) {
    const int b = blockIdx.x;
    const int t0 = blockIdx.y * 128;
    const int tid = threadIdx.x;
    __shared__ float ws[128];
    ws[tid] = out[B_ * D_ + b * T_ + t0 + tid];
    __syncthreads();
    const float4* vp = (const float4*)(values + ((size_t)b * T_ + t0) * D_) + tid;
    float ax = 0.f, ay = 0.f, az = 0.f, aw = 0.f;
#pragma unroll 4
    for (int tt = 0; tt < 128; tt++) {
        float w = ws[tt];
        float4 v = vp[tt * 128];
        ax += w * v.x; ay += w * v.y; az += w * v.z; aw += w * v.w;
    }
    float* o = out + b * D_ + tid * 4;
    atomicAdd(o + 0, ax);
    atomicAdd(o + 1, ay);
    atomicAdd(o + 2, az);
    atomicAdd(o + 3, aw);
}

// ---------------------------------------------------------------------------
extern "C" void kernel_launch(void* const* d_in, const int* in_sizes, int n_in,
                              void* d_out, int out_size) {
    const float* values = (const float*)d_in[0];
    const float* query  = (const float*)d_in[1];
    const float* W1     = (const float*)d_in[2];
    const float* b1     = (const float*)d_in[3];
    const float* W2     = (const float*)d_in[4];
    const float* b2     = (const float*)d_in[5];
    const float* V      = (const float*)d_in[6];
    // d_in[7] = bV: softmax shift-invariant -> unused
    float* out = (float*)d_out;

    cudaFuncSetAttribute(score_kernel,
                         cudaFuncAttributeMaxDynamicSharedMemorySize, SMEM_TOTAL);

    w1cvt_kernel<<<D_, U_>>>(W1);
    projq_kernel<<<B_, U_>>>(query, W2, b1, b2);
    score_kernel<<<(B_ * T_) / MT, 256, SMEM_TOTAL>>>(values, V);
    softmax_kernel<<<B_, 256>>>(out);
    context_kernel<<<dim3(B_, 16), 128>>>(values, out);
}